// round 16
// baseline (speedup 1.0000x reference)
#include <cuda_runtime.h>
#include <cuda_fp16.h>
#include <math.h>
#include <stdint.h>

#define BB 2
#define NN 2048
#define DIM 1024
#define HEADS 16
#define DH 64
#define RD 128
#define NT (BB*NN)
#define KD 1024            // projection K (hi-only fp16)
#define NCH 32             // 32-half chunks per K=1024

// ---------------- scratch (static device globals; no allocation) ------------
__device__ float g_qx[(size_t)NT*DIM];       // x @ Wq_x^T
__device__ float g_qa[(size_t)NT*DIM];       // a @ Wq_a^T
__device__ float g_kvx[(size_t)NT*2*DH];     // x @ Wkv_x^T
__device__ float g_kva[(size_t)NT*2*DH];     // a @ Wkv_a^T
__device__ __half g_Qh[(size_t)BB*HEADS*NN*RD]; // pre-scaled log2e/sqrt(128)
__device__ __half g_Kh[(size_t)NT*RD];
__device__ __half g_Vh[(size_t)NT*RD];
__device__ float g_cos[NN*DH];
__device__ float g_sin[NN*DH];
__device__ float g_invf[DH];

// fp16-cast operands
__device__ __half g_xe[(size_t)NT*KD];
__device__ __half g_ae[(size_t)NT*KD];
__device__ __half g_wqxe[(size_t)DIM*KD];
__device__ __half g_wqae[(size_t)DIM*KD];
__device__ __half g_wkxe[(size_t)2*DH*KD];
__device__ __half g_wkae[(size_t)2*DH*KD];

// ---------------- RoPE tables ----------------------------------------------
__global__ void rope_invf_kernel() {
    int j = threadIdx.x;
    if (j < DH) g_invf[j] = (float)pow(10000.0, -(double)j / 64.0);
}

__global__ void rope_table_kernel() {
    int i = blockIdx.x * blockDim.x + threadIdx.x;
    if (i >= NN * DH) return;
    int n = i >> 6, j = i & 63;
    float ang = (float)n * g_invf[j];        // fp32 multiply, as the reference
    const float HI = 6.28318548202514648f;
    const float LO = -1.7484556e-7f;
    float k = rintf(ang * 0.15915494309189535f);
    float r = fmaf(-k, HI, ang);
    r = fmaf(-k, LO, r);                     // r in [-pi, pi], err ~2e-7
    g_cos[i] = cosf(r);
    g_sin[i] = sinf(r);
}

// ---------------- fp16 cast (all 6 tensors, one launch) ---------------------
#define XV8   (NT*DIM/8)       // 524288
#define WQV8  (DIM*DIM/8)      // 131072
#define WKV8  (2*DH*DIM/8)     // 16384

__device__ __forceinline__ void cast_one8(const float* __restrict__ src,
                                          __half* __restrict__ dst, int i8) {
    int base = i8 * 8;
    const float* s = &src[base];
    float4 v0 = *reinterpret_cast<const float4*>(s);
    float4 v1 = *reinterpret_cast<const float4*>(s + 4);
    __half2 h0 = __floats2half2_rn(v0.x, v0.y);
    __half2 h1 = __floats2half2_rn(v0.z, v0.w);
    __half2 h2 = __floats2half2_rn(v1.x, v1.y);
    __half2 h3 = __floats2half2_rn(v1.z, v1.w);
    uint4 hv = make_uint4(*reinterpret_cast<uint32_t*>(&h0), *reinterpret_cast<uint32_t*>(&h1),
                          *reinterpret_cast<uint32_t*>(&h2), *reinterpret_cast<uint32_t*>(&h3));
    *reinterpret_cast<uint4*>(&dst[base]) = hv;
}

__global__ void expand_all_kernel(const float* __restrict__ x, const float* __restrict__ a,
                                  const float* __restrict__ wqx, const float* __restrict__ wqa,
                                  const float* __restrict__ wkx, const float* __restrict__ wka) {
    int i = blockIdx.x * blockDim.x + threadIdx.x;
    if (i < XV8)  { cast_one8(x,   g_xe,   i); return; }
    i -= XV8;
    if (i < XV8)  { cast_one8(a,   g_ae,   i); return; }
    i -= XV8;
    if (i < WQV8) { cast_one8(wqx, g_wqxe, i); return; }
    i -= WQV8;
    if (i < WQV8) { cast_one8(wqa, g_wqae, i); return; }
    i -= WQV8;
    if (i < WKV8) { cast_one8(wkx, g_wkxe, i); return; }
    i -= WKV8;
    if (i < WKV8) { cast_one8(wka, g_wkae, i); }
}

// ---------------- MMA helpers ----------------------------------------------
#define LDSM4(R0,R1,R2,R3,ADDR) \
    asm volatile("ldmatrix.sync.aligned.m8n8.x4.shared.b16 {%0,%1,%2,%3}, [%4];" \
        : "=r"(R0),"=r"(R1),"=r"(R2),"=r"(R3) : "r"(ADDR))
#define LDSM4T(R0,R1,R2,R3,ADDR) \
    asm volatile("ldmatrix.sync.aligned.m8n8.x4.trans.shared.b16 {%0,%1,%2,%3}, [%4];" \
        : "=r"(R0),"=r"(R1),"=r"(R2),"=r"(R3) : "r"(ADDR))
#define MMA16816(C, A, B0, B1) \
    asm volatile("mma.sync.aligned.m16n8k16.row.col.f32.f16.f16.f32 " \
        "{%0,%1,%2,%3},{%4,%5,%6,%7},{%8,%9},{%0,%1,%2,%3};" \
        : "+f"((C)[0]),"+f"((C)[1]),"+f"((C)[2]),"+f"((C)[3]) \
        : "r"((A)[0]),"r"((A)[1]),"r"((A)[2]),"r"((A)[3]), "r"(B0),"r"(B1))
#define CP_ASYNC16(DST, SRC) \
    asm volatile("cp.async.cg.shared.global [%0], [%1], 16;\n" :: "r"(DST), "l"(SRC))
#define CP_COMMIT() asm volatile("cp.async.commit_group;\n")

// ---------------- unified projection GEMM: 128x128 tiles, 256 thr, 4 stages -
// Y[M,Nout] = A[M,KD] @ B[Nout,KD]^T, fp32 out.  All hi-only fp16, K=1024.
#define GP 40   // smem row pitch in halves (32 data + 8 pad)
#define STG_H (128 * GP)        // halves per (A or B) stage
#define NSTAGE 4

__global__ void __launch_bounds__(256, 2) proj_kernel() {
    extern __shared__ __half ps[];
    __half* sA = ps;                    // [NSTAGE][128*GP]
    __half* sB = ps + NSTAGE * STG_H;   // [NSTAGE][128*GP]

    const int tid = threadIdx.x, lane = tid & 31, w = tid >> 5;
    const int wm = w & 3, wn = w >> 2;

    const __half* Ag; const __half* Bg; float* Y;
    int Nout, bm0, bn0;
    {
        int id = blockIdx.x;
        if (id < 512) {               // Q projections
            int which = id >> 8;
            int rem = id & 255;
            int mb = rem >> 3, nb = rem & 7;
            Ag = which ? g_ae : g_xe;
            Bg = which ? g_wqae : g_wqxe;
            Y  = which ? g_qa : g_qx;
            Nout = DIM; bm0 = mb * 128; bn0 = nb * 128;
        } else {                      // KV projections
            int id2 = id - 512;
            int which = id2 >> 5, mb = id2 & 31;
            Ag = which ? g_ae : g_xe;
            Bg = which ? g_wkae : g_wkxe;
            Y  = which ? g_kva : g_kvx;
            Nout = 128; bm0 = mb * 128; bn0 = 0;
        }
        Ag += (size_t)bm0 * KD;
        Bg += (size_t)bn0 * KD;
    }

    auto load_chunk = [&](int stg, int k0) {
        #pragma unroll
        for (int p = 0; p < 2; p++) {
            int idx = tid + p * 256;
            int row = idx >> 2, c8 = idx & 3;
            uint32_t da = (uint32_t)__cvta_generic_to_shared(&sA[stg * STG_H + row * GP + c8 * 8]);
            CP_ASYNC16(da, Ag + (size_t)row * KD + k0 + c8 * 8);
            uint32_t db = (uint32_t)__cvta_generic_to_shared(&sB[stg * STG_H + row * GP + c8 * 8]);
            CP_ASYNC16(db, Bg + (size_t)row * KD + k0 + c8 * 8);
        }
    };

    float c[2][8][4] = {};

    #pragma unroll
    for (int s = 0; s < NSTAGE - 1; s++) {
        load_chunk(s, s * 32);
        CP_COMMIT();
    }

    for (int ch = 0; ch < NCH; ch++) {
        if (ch + NSTAGE - 1 < NCH) {
            load_chunk((ch + NSTAGE - 1) & (NSTAGE - 1), (ch + NSTAGE - 1) * 32);
            CP_COMMIT();
            asm volatile("cp.async.wait_group %0;\n" :: "n"(NSTAGE - 1));
        } else {
            asm volatile("cp.async.wait_group 0;\n");
        }
        __syncthreads();
        const __half* cA = sA + (ch & (NSTAGE - 1)) * STG_H;
        const __half* cB = sB + (ch & (NSTAGE - 1)) * STG_H;
        #pragma unroll
        for (int kk = 0; kk < 2; kk++) {
            uint32_t a[2][4], bf[4][4];
            #pragma unroll
            for (int mt = 0; mt < 2; mt++) {
                uint32_t addr = (uint32_t)__cvta_generic_to_shared(
                    &cA[(wm * 32 + mt * 16 + (lane & 15)) * GP + ((lane >> 4) << 3) + kk * 16]);
                LDSM4(a[mt][0], a[mt][1], a[mt][2], a[mt][3], addr);
            }
            #pragma unroll
            for (int nt = 0; nt < 4; nt++) {
                uint32_t addr = (uint32_t)__cvta_generic_to_shared(
                    &cB[(wn * 64 + nt * 16 + ((lane & 7) + ((lane >> 4) << 3))) * GP + (lane & 8) + kk * 16]);
                LDSM4(bf[nt][0], bf[nt][1], bf[nt][2], bf[nt][3], addr);
            }
            #pragma unroll
            for (int mt = 0; mt < 2; mt++)
                #pragma unroll
                for (int nt = 0; nt < 4; nt++) {
                    MMA16816(c[mt][2 * nt],     a[mt], bf[nt][0], bf[nt][1]);
                    MMA16816(c[mt][2 * nt + 1], a[mt], bf[nt][2], bf[nt][3]);
                }
        }
        __syncthreads();
    }

    #pragma unroll
    for (int mt = 0; mt < 2; mt++) {
        int r0 = bm0 + wm * 32 + mt * 16 + (lane >> 2);
        #pragma unroll
        for (int n8 = 0; n8 < 8; n8++) {
            int col = bn0 + wn * 64 + n8 * 8 + 2 * (lane & 3);
            *reinterpret_cast<float2*>(&Y[(size_t)r0 * Nout + col]) =
                make_float2(c[mt][n8][0], c[mt][n8][1]);
            *reinterpret_cast<float2*>(&Y[(size_t)(r0 + 8) * Nout + col]) =
                make_float2(c[mt][n8][2], c[mt][n8][3]);
        }
    }
}

// ---------------- prep: l2norm + scale + concat + rotary -> fp16 -----------
// Q is additionally scaled by log2(e)/sqrt(128) so attention can use exp2.
__global__ void prep_kernel(const float* __restrict__ qx_scale,
                            const float* __restrict__ qa_scale,
                            const float* __restrict__ kx_scale,
                            const float* __restrict__ ka_scale) {
    int t = blockIdx.x;                 // global token 0..4095
    int b = t >> 11, n = t & (NN - 1);
    int w = threadIdx.x >> 5, l = threadIdx.x & 31;

    float c0 = g_cos[n * DH + l],      s0 = g_sin[n * DH + l];
    float c1 = g_cos[n * DH + l + 32], s1 = g_sin[n * DH + l + 32];
    const float SC = 0.08838834764831845f * 1.44269504088896341f; // log2e/sqrt(128)

    if (w < HEADS) {
        int h = w;
        const float* px = &g_qx[(size_t)t * DIM + h * DH];
        float x0 = px[l], x1 = px[l + 32];
        float sx = x0 * x0 + x1 * x1;
        #pragma unroll
        for (int o = 16; o; o >>= 1) sx += __shfl_xor_sync(0xFFFFFFFFu, sx, o);
        float rnx = 1.0f / fmaxf(sqrtf(sx), 1e-12f);
        float qx0 = x0 * rnx * qx_scale[h * DH + l];
        float qx1 = x1 * rnx * qx_scale[h * DH + l + 32];

        const float* pa = &g_qa[(size_t)t * DIM + h * DH];
        float a0 = pa[l], a1 = pa[l + 32];
        float sa = a0 * a0 + a1 * a1;
        #pragma unroll
        for (int o = 16; o; o >>= 1) sa += __shfl_xor_sync(0xFFFFFFFFu, sa, o);
        float rna = 1.0f / fmaxf(sqrtf(sa), 1e-12f);
        float qa0 = a0 * rna * qa_scale[h * DH + l];
        float qa1 = a1 * rna * qa_scale[h * DH + l + 32];

        __half* pq = &g_Qh[(((size_t)b * HEADS + h) * NN + n) * RD];
        pq[l]      = __float2half_rn(SC * (qx0 * c0 - qa0 * s0));
        pq[l + 64] = __float2half_rn(SC * (qa0 * c0 + qx0 * s0));
        pq[l + 32] = __float2half_rn(SC * (qx1 * c1 - qa1 * s1));
        pq[l + 96] = __float2half_rn(SC * (qa1 * c1 + qx1 * s1));
    } else if (w == 16) {   // K
        const float* px = &g_kvx[(size_t)t * 2 * DH];
        float x0 = px[l], x1 = px[l + 32];
        float sx = x0 * x0 + x1 * x1;
        #pragma unroll
        for (int o = 16; o; o >>= 1) sx += __shfl_xor_sync(0xFFFFFFFFu, sx, o);
        float rnx = 1.0f / fmaxf(sqrtf(sx), 1e-12f);
        float kx0 = x0 * rnx * kx_scale[l];
        float kx1 = x1 * rnx * kx_scale[l + 32];

        const float* pa = &g_kva[(size_t)t * 2 * DH];
        float a0 = pa[l], a1 = pa[l + 32];
        float sa = a0 * a0 + a1 * a1;
        #pragma unroll
        for (int o = 16; o; o >>= 1) sa += __shfl_xor_sync(0xFFFFFFFFu, sa, o);
        float rna = 1.0f / fmaxf(sqrtf(sa), 1e-12f);
        float ka0 = a0 * rna * ka_scale[l];
        float ka1 = a1 * rna * ka_scale[l + 32];

        __half* pk = &g_Kh[(size_t)t * RD];
        pk[l]      = __float2half_rn(kx0 * c0 - ka0 * s0);
        pk[l + 64] = __float2half_rn(ka0 * c0 + kx0 * s0);
        pk[l + 32] = __float2half_rn(kx1 * c1 - ka1 * s1);
        pk[l + 96] = __float2half_rn(ka1 * c1 + kx1 * s1);
    } else {                // V (no norm, no rotary)
        const float* px = &g_kvx[(size_t)t * 2 * DH + DH];
        const float* pa = &g_kva[(size_t)t * 2 * DH + DH];
        __half* pv = &g_Vh[(size_t)t * RD];
        pv[l]      = __float2half_rn(px[l]);
        pv[l + 32] = __float2half_rn(px[l + 32]);
        pv[l + 64] = __float2half_rn(pa[l]);
        pv[l + 96] = __float2half_rn(pa[l + 32]);
    }
}

// ---------------- tensor-core flash attention (fixed-max softmax) -----------
// Q/K l2-normalized -> |S_log2| <= ~0.26: no overflow possible, so softmax
// uses fixed m=0: p = exp2(s), l accumulated per-thread, ONE reduction at end.
// No running max, no alpha rescale of O — removes the serial softmax chain.
#define PADW 136
#define TILE_H (64 * PADW)   // halves per buffer

__device__ __forceinline__ uint32_t pack_f16(float lo, float hi) {
    __half2 p = __floats2half2_rn(lo, hi);
    return *reinterpret_cast<uint32_t*>(&p);
}

__global__ void __launch_bounds__(256) attn_mma_kernel(float* __restrict__ out) {
    extern __shared__ __half sm[];
    // buffers: sK0 @0, sK1 @TILE_H, sV0 @2*TILE_H, sV1 @3*TILE_H

    const int qb = blockIdx.x, h = blockIdx.y, b = blockIdx.z;
    const int tid = threadIdx.x, w = tid >> 5, lane = tid & 31;
    const int q0 = w * 16;

    // ---- stage Q tile (128x128 fp16) into smem (aliases sK0|sK1), preload a-frags
    const __half* Qg = g_Qh + (((size_t)b * HEADS + h) * NN + (size_t)qb * 128) * RD;
    for (int i = tid; i < 128 * 16; i += 256) {
        int r = i >> 4, c = i & 15;
        *reinterpret_cast<uint4*>(&sm[r * PADW + c * 8]) =
            *reinterpret_cast<const uint4*>(&Qg[r * RD + c * 8]);
    }
    __syncthreads();

    uint32_t qa[8][4];
    {
        uint32_t qbase = (uint32_t)__cvta_generic_to_shared(
            &sm[(q0 + (lane & 15)) * PADW + ((lane >> 4) << 3)]);
        #pragma unroll
        for (int ks = 0; ks < 8; ks++) {
            uint32_t addr = qbase + ks * 16 * 2;
            LDSM4(qa[ks][0], qa[ks][1], qa[ks][2], qa[ks][3], addr);
        }
    }
    __syncthreads();   // Q reads done; smem reusable for K/V

    float l_[2] = {0.0f, 0.0f};
    float o[16][4] = {};

    const __half* Kg = g_Kh + (size_t)b * NN * RD;
    const __half* Vg = g_Vh + (size_t)b * NN * RD;

    const uint32_t kbase0 = (uint32_t)__cvta_generic_to_shared(
        &sm[((lane & 7) + ((lane >> 4) << 3)) * PADW + (lane & 8)]);
    const uint32_t vbase0 = (uint32_t)__cvta_generic_to_shared(
        &sm[2 * TILE_H + (lane & 15) * PADW + ((lane >> 4) << 3)]);

    auto prefetch = [&](int kt, int buf) {
        const __half* Kt = Kg + (size_t)kt * 64 * RD;
        const __half* Vt = Vg + (size_t)kt * 64 * RD;
        __half* dK = sm + buf * TILE_H;
        __half* dV = sm + (2 + buf) * TILE_H;
        #pragma unroll
        for (int p = 0; p < 4; p++) {
            int idx = tid + p * 256;
            int r = idx >> 4, c8 = idx & 15;
            uint32_t dk = (uint32_t)__cvta_generic_to_shared(&dK[r * PADW + c8 * 8]);
            CP_ASYNC16(dk, Kt + (size_t)r * RD + c8 * 8);
            uint32_t dv = (uint32_t)__cvta_generic_to_shared(&dV[r * PADW + c8 * 8]);
            CP_ASYNC16(dv, Vt + (size_t)r * RD + c8 * 8);
        }
    };

    prefetch(0, 0);
    CP_COMMIT();

    for (int kt = 0; kt < NN / 64; kt++) {
        if (kt + 1 < NN / 64) {
            prefetch(kt + 1, (kt + 1) & 1);
            CP_COMMIT();
            asm volatile("cp.async.wait_group 1;\n");
        } else {
            asm volatile("cp.async.wait_group 0;\n");
        }
        __syncthreads();   // tile kt visible to all warps

        const uint32_t bufoff = (uint32_t)((kt & 1) * TILE_H * 2);  // bytes
        const uint32_t kbase = kbase0 + bufoff;
        const uint32_t vbase = vbase0 + bufoff;

        // ---- S = Q K^T  (S in log2 units, |S| <= ~0.3)
        float s[8][4] = {};
        #pragma unroll
        for (int ks = 0; ks < 8; ks++) {
            #pragma unroll
            for (int np = 0; np < 4; np++) {
                uint32_t addr = kbase + (uint32_t)((np * 16 * PADW + ks * 16) * 2);
                uint32_t b0, b1, b2, b3;
                LDSM4(b0, b1, b2, b3, addr);
                MMA16816(s[2 * np],     qa[ks], b0, b1);
                MMA16816(s[2 * np + 1], qa[ks], b2, b3);
            }
        }

        // ---- fixed-max softmax: p = exp2(s), accumulate l per-thread
        #pragma unroll
        for (int nt = 0; nt < 8; nt++) {
            #pragma unroll
            for (int e = 0; e < 4; e++) {
                float p = exp2f(s[nt][e]);
                s[nt][e] = p;
                l_[e >> 1] += p;
            }
        }

        // ---- O += P V
        #pragma unroll
        for (int ks2 = 0; ks2 < 4; ks2++) {
            uint32_t pa[4];
            pa[0] = pack_f16(s[2 * ks2][0],     s[2 * ks2][1]);
            pa[1] = pack_f16(s[2 * ks2][2],     s[2 * ks2][3]);
            pa[2] = pack_f16(s[2 * ks2 + 1][0], s[2 * ks2 + 1][1]);
            pa[3] = pack_f16(s[2 * ks2 + 1][2], s[2 * ks2 + 1][3]);
            #pragma unroll
            for (int np = 0; np < 8; np++) {
                uint32_t addr = vbase + (uint32_t)((ks2 * 16 * PADW + np * 16) * 2);
                uint32_t v0, v1, v2, v3;
                LDSM4T(v0, v1, v2, v3, addr);
                MMA16816(o[2 * np],     pa, v0, v1);
                MMA16816(o[2 * np + 1], pa, v2, v3);
            }
        }
        __syncthreads();   // all warps done reading buf[kt&1] before kt+2 prefetch
    }

    // ---- one final l reduction across the quad, then normalize and store
    #pragma unroll
    for (int r = 0; r < 2; r++) {
        l_[r] += __shfl_xor_sync(0xFFFFFFFFu, l_[r], 1);
        l_[r] += __shfl_xor_sync(0xFFFFFFFFu, l_[r], 2);
    }
    float rl0 = 1.0f / l_[0], rl1 = 1.0f / l_[1];
    int qrow = qb * 128 + q0 + (lane >> 2);
    #pragma unroll
    for (int j = 0; j < 16; j++) {
        int d = h * RD + j * 8 + 2 * (lane & 3);
        float* p0 = &out[((size_t)(b * NN + qrow)) * (HEADS * RD) + d];
        float* p1 = &out[((size_t)(b * NN + qrow + 8)) * (HEADS * RD) + d];
        *reinterpret_cast<float2*>(p0) = make_float2(o[j][0] * rl0, o[j][1] * rl0);
        *reinterpret_cast<float2*>(p1) = make_float2(o[j][2] * rl1, o[j][3] * rl1);
    }
}

// ---------------- launch ---------------------------------------------------
extern "C" void kernel_launch(void* const* d_in, const int* in_sizes, int n_in,
                              void* d_out, int out_size) {
    const float* x        = (const float*)d_in[0];
    const float* a        = (const float*)d_in[1];
    const float* Wq_x     = (const float*)d_in[2];
    const float* Wkv_x    = (const float*)d_in[3];
    const float* Wq_a     = (const float*)d_in[4];
    const float* Wkv_a    = (const float*)d_in[5];
    const float* qx_scale = (const float*)d_in[6];
    const float* qa_scale = (const float*)d_in[7];
    const float* kx_scale = (const float*)d_in[8];
    const float* ka_scale = (const float*)d_in[9];
    float* out = (float*)d_out;

    rope_invf_kernel<<<1, 64>>>();
    rope_table_kernel<<<(NN * DH + 255) / 256, 256>>>();

    // one launch: all fp16 casts (8 elems/thread)
    int cast_v8 = 2 * XV8 + 2 * WQV8 + 2 * WKV8;
    expand_all_kernel<<<(cast_v8 + 255) / 256, 256>>>(x, a, Wq_x, Wq_a, Wkv_x, Wkv_a);

    // one launch: all projections, hi-only K=1024 (512 Q + 64 KV, 2 CTAs/SM)
    int proj_smem = 2 * NSTAGE * STG_H * (int)sizeof(__half);  // 81920 B
    cudaFuncSetAttribute(proj_kernel, cudaFuncAttributeMaxDynamicSharedMemorySize, proj_smem);
    proj_kernel<<<576, 256, proj_smem>>>();

    prep_kernel<<<NT, 18 * 32>>>(qx_scale, qa_scale, kx_scale, ka_scale);

    int smem_bytes = 4 * TILE_H * (int)sizeof(__half);  // 69632 B
    cudaFuncSetAttribute(attn_mma_kernel, cudaFuncAttributeMaxDynamicSharedMemorySize, smem_bytes);
    attn_mma_kernel<<<dim3(NN / 128, HEADS, BB), 256, smem_bytes>>>(out);
}

// round 17
// speedup vs baseline: 1.1105x; 1.1105x over previous
#include <cuda_runtime.h>
#include <cuda_fp16.h>
#include <math.h>
#include <stdint.h>

#define BB 2
#define NN 2048
#define DIM 1024
#define HEADS 16
#define DH 64
#define RD 128
#define NT (BB*NN)
#define KD 1024            // projection K (hi-only fp16)
#define NCH 32             // 32-half chunks per K=1024

// ---------------- scratch (static device globals; no allocation) ------------
__device__ float g_qx[(size_t)NT*DIM];       // x @ Wq_x^T
__device__ float g_qa[(size_t)NT*DIM];       // a @ Wq_a^T
__device__ float g_kvx[(size_t)NT*2*DH];     // x @ Wkv_x^T
__device__ float g_kva[(size_t)NT*2*DH];     // a @ Wkv_a^T
__device__ __half g_Qh[(size_t)BB*HEADS*NN*RD]; // pre-scaled log2e/sqrt(128)
__device__ __half g_Kh[(size_t)NT*RD];
__device__ __half g_Vh[(size_t)NT*RD];
__device__ float g_cos[NN*DH];
__device__ float g_sin[NN*DH];
__device__ float g_invf[DH];

// fp16-cast operands
__device__ __half g_xe[(size_t)NT*KD];
__device__ __half g_ae[(size_t)NT*KD];
__device__ __half g_wqxe[(size_t)DIM*KD];
__device__ __half g_wqae[(size_t)DIM*KD];
__device__ __half g_wkxe[(size_t)2*DH*KD];
__device__ __half g_wkae[(size_t)2*DH*KD];

// ---------------- RoPE tables ----------------------------------------------
__global__ void rope_invf_kernel() {
    int j = threadIdx.x;
    if (j < DH) g_invf[j] = (float)pow(10000.0, -(double)j / 64.0);
}

__global__ void rope_table_kernel() {
    int i = blockIdx.x * blockDim.x + threadIdx.x;
    if (i >= NN * DH) return;
    int n = i >> 6, j = i & 63;
    float ang = (float)n * g_invf[j];        // fp32 multiply, as the reference
    const float HI = 6.28318548202514648f;
    const float LO = -1.7484556e-7f;
    float k = rintf(ang * 0.15915494309189535f);
    float r = fmaf(-k, HI, ang);
    r = fmaf(-k, LO, r);                     // r in [-pi, pi], err ~2e-7
    g_cos[i] = cosf(r);
    g_sin[i] = sinf(r);
}

// ---------------- fp16 cast (all 6 tensors, one launch) ---------------------
#define XV8   (NT*DIM/8)       // 524288
#define WQV8  (DIM*DIM/8)      // 131072
#define WKV8  (2*DH*DIM/8)     // 16384

__device__ __forceinline__ void cast_one8(const float* __restrict__ src,
                                          __half* __restrict__ dst, int i8) {
    int base = i8 * 8;
    const float* s = &src[base];
    float4 v0 = *reinterpret_cast<const float4*>(s);
    float4 v1 = *reinterpret_cast<const float4*>(s + 4);
    __half2 h0 = __floats2half2_rn(v0.x, v0.y);
    __half2 h1 = __floats2half2_rn(v0.z, v0.w);
    __half2 h2 = __floats2half2_rn(v1.x, v1.y);
    __half2 h3 = __floats2half2_rn(v1.z, v1.w);
    uint4 hv = make_uint4(*reinterpret_cast<uint32_t*>(&h0), *reinterpret_cast<uint32_t*>(&h1),
                          *reinterpret_cast<uint32_t*>(&h2), *reinterpret_cast<uint32_t*>(&h3));
    *reinterpret_cast<uint4*>(&dst[base]) = hv;
}

__global__ void expand_all_kernel(const float* __restrict__ x, const float* __restrict__ a,
                                  const float* __restrict__ wqx, const float* __restrict__ wqa,
                                  const float* __restrict__ wkx, const float* __restrict__ wka) {
    int i = blockIdx.x * blockDim.x + threadIdx.x;
    if (i < XV8)  { cast_one8(x,   g_xe,   i); return; }
    i -= XV8;
    if (i < XV8)  { cast_one8(a,   g_ae,   i); return; }
    i -= XV8;
    if (i < WQV8) { cast_one8(wqx, g_wqxe, i); return; }
    i -= WQV8;
    if (i < WQV8) { cast_one8(wqa, g_wqae, i); return; }
    i -= WQV8;
    if (i < WKV8) { cast_one8(wkx, g_wkxe, i); return; }
    i -= WKV8;
    if (i < WKV8) { cast_one8(wka, g_wkae, i); }
}

// ---------------- MMA helpers ----------------------------------------------
#define LDSM4(R0,R1,R2,R3,ADDR) \
    asm volatile("ldmatrix.sync.aligned.m8n8.x4.shared.b16 {%0,%1,%2,%3}, [%4];" \
        : "=r"(R0),"=r"(R1),"=r"(R2),"=r"(R3) : "r"(ADDR))
#define LDSM4T(R0,R1,R2,R3,ADDR) \
    asm volatile("ldmatrix.sync.aligned.m8n8.x4.trans.shared.b16 {%0,%1,%2,%3}, [%4];" \
        : "=r"(R0),"=r"(R1),"=r"(R2),"=r"(R3) : "r"(ADDR))
#define MMA16816(C, A, B0, B1) \
    asm volatile("mma.sync.aligned.m16n8k16.row.col.f32.f16.f16.f32 " \
        "{%0,%1,%2,%3},{%4,%5,%6,%7},{%8,%9},{%0,%1,%2,%3};" \
        : "+f"((C)[0]),"+f"((C)[1]),"+f"((C)[2]),"+f"((C)[3]) \
        : "r"((A)[0]),"r"((A)[1]),"r"((A)[2]),"r"((A)[3]), "r"(B0),"r"(B1))
#define CP_ASYNC16(DST, SRC) \
    asm volatile("cp.async.cg.shared.global [%0], [%1], 16;\n" :: "r"(DST), "l"(SRC))
#define CP_COMMIT() asm volatile("cp.async.commit_group;\n")

// ---------------- unified projection GEMM: 128x128 tiles, 256 thr, 4 stages -
// Y[M,Nout] = A[M,KD] @ B[Nout,KD]^T, fp32 out.  All hi-only fp16, K=1024.
#define GP 40   // smem row pitch in halves (32 data + 8 pad)
#define STG_H (128 * GP)        // halves per (A or B) stage
#define NSTAGE 4

__global__ void __launch_bounds__(256, 2) proj_kernel() {
    extern __shared__ __half ps[];
    __half* sA = ps;                    // [NSTAGE][128*GP]
    __half* sB = ps + NSTAGE * STG_H;   // [NSTAGE][128*GP]

    const int tid = threadIdx.x, lane = tid & 31, w = tid >> 5;
    const int wm = w & 3, wn = w >> 2;

    const __half* Ag; const __half* Bg; float* Y;
    int Nout, bm0, bn0;
    {
        int id = blockIdx.x;
        if (id < 512) {               // Q projections
            int which = id >> 8;
            int rem = id & 255;
            int mb = rem >> 3, nb = rem & 7;
            Ag = which ? g_ae : g_xe;
            Bg = which ? g_wqae : g_wqxe;
            Y  = which ? g_qa : g_qx;
            Nout = DIM; bm0 = mb * 128; bn0 = nb * 128;
        } else {                      // KV projections
            int id2 = id - 512;
            int which = id2 >> 5, mb = id2 & 31;
            Ag = which ? g_ae : g_xe;
            Bg = which ? g_wkae : g_wkxe;
            Y  = which ? g_kva : g_kvx;
            Nout = 128; bm0 = mb * 128; bn0 = 0;
        }
        Ag += (size_t)bm0 * KD;
        Bg += (size_t)bn0 * KD;
    }

    auto load_chunk = [&](int stg, int k0) {
        #pragma unroll
        for (int p = 0; p < 2; p++) {
            int idx = tid + p * 256;
            int row = idx >> 2, c8 = idx & 3;
            uint32_t da = (uint32_t)__cvta_generic_to_shared(&sA[stg * STG_H + row * GP + c8 * 8]);
            CP_ASYNC16(da, Ag + (size_t)row * KD + k0 + c8 * 8);
            uint32_t db = (uint32_t)__cvta_generic_to_shared(&sB[stg * STG_H + row * GP + c8 * 8]);
            CP_ASYNC16(db, Bg + (size_t)row * KD + k0 + c8 * 8);
        }
    };

    float c[2][8][4] = {};

    #pragma unroll
    for (int s = 0; s < NSTAGE - 1; s++) {
        load_chunk(s, s * 32);
        CP_COMMIT();
    }

    for (int ch = 0; ch < NCH; ch++) {
        if (ch + NSTAGE - 1 < NCH) {
            load_chunk((ch + NSTAGE - 1) & (NSTAGE - 1), (ch + NSTAGE - 1) * 32);
            CP_COMMIT();
            asm volatile("cp.async.wait_group %0;\n" :: "n"(NSTAGE - 1));
        } else {
            asm volatile("cp.async.wait_group 0;\n");
        }
        __syncthreads();
        const __half* cA = sA + (ch & (NSTAGE - 1)) * STG_H;
        const __half* cB = sB + (ch & (NSTAGE - 1)) * STG_H;
        #pragma unroll
        for (int kk = 0; kk < 2; kk++) {
            uint32_t a[2][4], bf[4][4];
            #pragma unroll
            for (int mt = 0; mt < 2; mt++) {
                uint32_t addr = (uint32_t)__cvta_generic_to_shared(
                    &cA[(wm * 32 + mt * 16 + (lane & 15)) * GP + ((lane >> 4) << 3) + kk * 16]);
                LDSM4(a[mt][0], a[mt][1], a[mt][2], a[mt][3], addr);
            }
            #pragma unroll
            for (int nt = 0; nt < 4; nt++) {
                uint32_t addr = (uint32_t)__cvta_generic_to_shared(
                    &cB[(wn * 64 + nt * 16 + ((lane & 7) + ((lane >> 4) << 3))) * GP + (lane & 8) + kk * 16]);
                LDSM4(bf[nt][0], bf[nt][1], bf[nt][2], bf[nt][3], addr);
            }
            #pragma unroll
            for (int mt = 0; mt < 2; mt++)
                #pragma unroll
                for (int nt = 0; nt < 4; nt++) {
                    MMA16816(c[mt][2 * nt],     a[mt], bf[nt][0], bf[nt][1]);
                    MMA16816(c[mt][2 * nt + 1], a[mt], bf[nt][2], bf[nt][3]);
                }
        }
        __syncthreads();
    }

    #pragma unroll
    for (int mt = 0; mt < 2; mt++) {
        int r0 = bm0 + wm * 32 + mt * 16 + (lane >> 2);
        #pragma unroll
        for (int n8 = 0; n8 < 8; n8++) {
            int col = bn0 + wn * 64 + n8 * 8 + 2 * (lane & 3);
            *reinterpret_cast<float2*>(&Y[(size_t)r0 * Nout + col]) =
                make_float2(c[mt][n8][0], c[mt][n8][1]);
            *reinterpret_cast<float2*>(&Y[(size_t)(r0 + 8) * Nout + col]) =
                make_float2(c[mt][n8][2], c[mt][n8][3]);
        }
    }
}

// ---------------- prep: l2norm + scale + concat + rotary -> fp16 -----------
// Q is additionally scaled by log2(e)/sqrt(128) so attention can use exp2.
__global__ void prep_kernel(const float* __restrict__ qx_scale,
                            const float* __restrict__ qa_scale,
                            const float* __restrict__ kx_scale,
                            const float* __restrict__ ka_scale) {
    int t = blockIdx.x;                 // global token 0..4095
    int b = t >> 11, n = t & (NN - 1);
    int w = threadIdx.x >> 5, l = threadIdx.x & 31;

    float c0 = g_cos[n * DH + l],      s0 = g_sin[n * DH + l];
    float c1 = g_cos[n * DH + l + 32], s1 = g_sin[n * DH + l + 32];
    const float SC = 0.08838834764831845f * 1.44269504088896341f; // log2e/sqrt(128)

    if (w < HEADS) {
        int h = w;
        const float* px = &g_qx[(size_t)t * DIM + h * DH];
        float x0 = px[l], x1 = px[l + 32];
        float sx = x0 * x0 + x1 * x1;
        #pragma unroll
        for (int o = 16; o; o >>= 1) sx += __shfl_xor_sync(0xFFFFFFFFu, sx, o);
        float rnx = 1.0f / fmaxf(sqrtf(sx), 1e-12f);
        float qx0 = x0 * rnx * qx_scale[h * DH + l];
        float qx1 = x1 * rnx * qx_scale[h * DH + l + 32];

        const float* pa = &g_qa[(size_t)t * DIM + h * DH];
        float a0 = pa[l], a1 = pa[l + 32];
        float sa = a0 * a0 + a1 * a1;
        #pragma unroll
        for (int o = 16; o; o >>= 1) sa += __shfl_xor_sync(0xFFFFFFFFu, sa, o);
        float rna = 1.0f / fmaxf(sqrtf(sa), 1e-12f);
        float qa0 = a0 * rna * qa_scale[h * DH + l];
        float qa1 = a1 * rna * qa_scale[h * DH + l + 32];

        __half* pq = &g_Qh[(((size_t)b * HEADS + h) * NN + n) * RD];
        pq[l]      = __float2half_rn(SC * (qx0 * c0 - qa0 * s0));
        pq[l + 64] = __float2half_rn(SC * (qa0 * c0 + qx0 * s0));
        pq[l + 32] = __float2half_rn(SC * (qx1 * c1 - qa1 * s1));
        pq[l + 96] = __float2half_rn(SC * (qa1 * c1 + qx1 * s1));
    } else if (w == 16) {   // K
        const float* px = &g_kvx[(size_t)t * 2 * DH];
        float x0 = px[l], x1 = px[l + 32];
        float sx = x0 * x0 + x1 * x1;
        #pragma unroll
        for (int o = 16; o; o >>= 1) sx += __shfl_xor_sync(0xFFFFFFFFu, sx, o);
        float rnx = 1.0f / fmaxf(sqrtf(sx), 1e-12f);
        float kx0 = x0 * rnx * kx_scale[l];
        float kx1 = x1 * rnx * kx_scale[l + 32];

        const float* pa = &g_kva[(size_t)t * 2 * DH];
        float a0 = pa[l], a1 = pa[l + 32];
        float sa = a0 * a0 + a1 * a1;
        #pragma unroll
        for (int o = 16; o; o >>= 1) sa += __shfl_xor_sync(0xFFFFFFFFu, sa, o);
        float rna = 1.0f / fmaxf(sqrtf(sa), 1e-12f);
        float ka0 = a0 * rna * ka_scale[l];
        float ka1 = a1 * rna * ka_scale[l + 32];

        __half* pk = &g_Kh[(size_t)t * RD];
        pk[l]      = __float2half_rn(kx0 * c0 - ka0 * s0);
        pk[l + 64] = __float2half_rn(ka0 * c0 + kx0 * s0);
        pk[l + 32] = __float2half_rn(kx1 * c1 - ka1 * s1);
        pk[l + 96] = __float2half_rn(ka1 * c1 + kx1 * s1);
    } else {                // V (no norm, no rotary)
        const float* px = &g_kvx[(size_t)t * 2 * DH + DH];
        const float* pa = &g_kva[(size_t)t * 2 * DH + DH];
        __half* pv = &g_Vh[(size_t)t * RD];
        pv[l]      = __float2half_rn(px[l]);
        pv[l + 32] = __float2half_rn(px[l + 32]);
        pv[l + 64] = __float2half_rn(pa[l]);
        pv[l + 96] = __float2half_rn(pa[l + 32]);
    }
}

// ---------------- tensor-core flash attention (2 CTAs/SM) -------------------
// Fixed-max softmax (|S_log2|<=0.3).  Q lives in its OWN smem region; a-frags
// re-ldmatrix'd per tile (+8 LDSM/warp/tile) to fit the 128-reg budget for
// 2 CTAs/SM.  smem/CTA = Q 34.8KB + K/V ring 69.6KB = 104.4KB.
#define PADW 136
#define TILE_H (64 * PADW)     // halves per K or V buffer
#define QH (128 * PADW)        // halves for Q region

__device__ __forceinline__ uint32_t pack_f16(float lo, float hi) {
    __half2 p = __floats2half2_rn(lo, hi);
    return *reinterpret_cast<uint32_t*>(&p);
}

__global__ void __launch_bounds__(256, 2) attn_mma_kernel(float* __restrict__ out) {
    extern __shared__ __half sm[];
    // layout: sQ @0 (QH), then sK0 @QH, sK1 @QH+TILE_H, sV0 @QH+2T, sV1 @QH+3T
    __half* ring = sm + QH;

    const int qb = blockIdx.x, h = blockIdx.y, b = blockIdx.z;
    const int tid = threadIdx.x, w = tid >> 5, lane = tid & 31;
    const int q0 = w * 16;

    // ---- stage Q tile (128x128 fp16) into dedicated smem region
    const __half* Qg = g_Qh + (((size_t)b * HEADS + h) * NN + (size_t)qb * 128) * RD;
    for (int i = tid; i < 128 * 16; i += 256) {
        int r = i >> 4, c = i & 15;
        *reinterpret_cast<uint4*>(&sm[r * PADW + c * 8]) =
            *reinterpret_cast<const uint4*>(&Qg[r * RD + c * 8]);
    }

    float l_[2] = {0.0f, 0.0f};
    float o[16][4] = {};

    const __half* Kg = g_Kh + (size_t)b * NN * RD;
    const __half* Vg = g_Vh + (size_t)b * NN * RD;

    const uint32_t qbase = (uint32_t)__cvta_generic_to_shared(
        &sm[(q0 + (lane & 15)) * PADW + ((lane >> 4) << 3)]);
    const uint32_t kbase0 = (uint32_t)__cvta_generic_to_shared(
        &ring[((lane & 7) + ((lane >> 4) << 3)) * PADW + (lane & 8)]);
    const uint32_t vbase0 = (uint32_t)__cvta_generic_to_shared(
        &ring[2 * TILE_H + (lane & 15) * PADW + ((lane >> 4) << 3)]);

    auto prefetch = [&](int kt, int buf) {
        const __half* Kt = Kg + (size_t)kt * 64 * RD;
        const __half* Vt = Vg + (size_t)kt * 64 * RD;
        __half* dK = ring + buf * TILE_H;
        __half* dV = ring + (2 + buf) * TILE_H;
        #pragma unroll
        for (int p = 0; p < 4; p++) {
            int idx = tid + p * 256;
            int r = idx >> 4, c8 = idx & 15;
            uint32_t dk = (uint32_t)__cvta_generic_to_shared(&dK[r * PADW + c8 * 8]);
            CP_ASYNC16(dk, Kt + (size_t)r * RD + c8 * 8);
            uint32_t dv = (uint32_t)__cvta_generic_to_shared(&dV[r * PADW + c8 * 8]);
            CP_ASYNC16(dv, Vt + (size_t)r * RD + c8 * 8);
        }
    };

    prefetch(0, 0);
    CP_COMMIT();
    __syncthreads();   // Q staged (also covered by later barrier, but needed before first QK)

    for (int kt = 0; kt < NN / 64; kt++) {
        if (kt + 1 < NN / 64) {
            prefetch(kt + 1, (kt + 1) & 1);
            CP_COMMIT();
            asm volatile("cp.async.wait_group 1;\n");
        } else {
            asm volatile("cp.async.wait_group 0;\n");
        }
        __syncthreads();   // tile kt visible to all warps

        const uint32_t bufoff = (uint32_t)((kt & 1) * TILE_H * 2);  // bytes
        const uint32_t kbase = kbase0 + bufoff;
        const uint32_t vbase = vbase0 + bufoff;

        // ---- S = Q K^T  (qa re-ldmatrix'd per ks; S in log2 units, |S|<=~0.3)
        float s[8][4] = {};
        #pragma unroll
        for (int ks = 0; ks < 8; ks++) {
            uint32_t qa[4];
            LDSM4(qa[0], qa[1], qa[2], qa[3], qbase + ks * 32);
            #pragma unroll
            for (int np = 0; np < 4; np++) {
                uint32_t addr = kbase + (uint32_t)((np * 16 * PADW + ks * 16) * 2);
                uint32_t b0, b1, b2, b3;
                LDSM4(b0, b1, b2, b3, addr);
                MMA16816(s[2 * np],     qa, b0, b1);
                MMA16816(s[2 * np + 1], qa, b2, b3);
            }
        }

        // ---- fixed-max softmax: p = exp2(s), accumulate l per-thread
        #pragma unroll
        for (int nt = 0; nt < 8; nt++) {
            #pragma unroll
            for (int e = 0; e < 4; e++) {
                float p = exp2f(s[nt][e]);
                s[nt][e] = p;
                l_[e >> 1] += p;
            }
        }

        // ---- O += P V
        #pragma unroll
        for (int ks2 = 0; ks2 < 4; ks2++) {
            uint32_t pa[4];
            pa[0] = pack_f16(s[2 * ks2][0],     s[2 * ks2][1]);
            pa[1] = pack_f16(s[2 * ks2][2],     s[2 * ks2][3]);
            pa[2] = pack_f16(s[2 * ks2 + 1][0], s[2 * ks2 + 1][1]);
            pa[3] = pack_f16(s[2 * ks2 + 1][2], s[2 * ks2 + 1][3]);
            #pragma unroll
            for (int np = 0; np < 8; np++) {
                uint32_t addr = vbase + (uint32_t)((ks2 * 16 * PADW + np * 16) * 2);
                uint32_t v0, v1, v2, v3;
                LDSM4T(v0, v1, v2, v3, addr);
                MMA16816(o[2 * np],     pa, v0, v1);
                MMA16816(o[2 * np + 1], pa, v2, v3);
            }
        }
        __syncthreads();   // all warps done reading buf[kt&1] before kt+2 prefetch
    }

    // ---- one final l reduction across the quad, then normalize and store
    #pragma unroll
    for (int r = 0; r < 2; r++) {
        l_[r] += __shfl_xor_sync(0xFFFFFFFFu, l_[r], 1);
        l_[r] += __shfl_xor_sync(0xFFFFFFFFu, l_[r], 2);
    }
    float rl0 = 1.0f / l_[0], rl1 = 1.0f / l_[1];
    int qrow = qb * 128 + q0 + (lane >> 2);
    #pragma unroll
    for (int j = 0; j < 16; j++) {
        int d = h * RD + j * 8 + 2 * (lane & 3);
        float* p0 = &out[((size_t)(b * NN + qrow)) * (HEADS * RD) + d];
        float* p1 = &out[((size_t)(b * NN + qrow + 8)) * (HEADS * RD) + d];
        *reinterpret_cast<float2*>(p0) = make_float2(o[j][0] * rl0, o[j][1] * rl0);
        *reinterpret_cast<float2*>(p1) = make_float2(o[j][2] * rl1, o[j][3] * rl1);
    }
}

// ---------------- launch ---------------------------------------------------
extern "C" void kernel_launch(void* const* d_in, const int* in_sizes, int n_in,
                              void* d_out, int out_size) {
    const float* x        = (const float*)d_in[0];
    const float* a        = (const float*)d_in[1];
    const float* Wq_x     = (const float*)d_in[2];
    const float* Wkv_x    = (const float*)d_in[3];
    const float* Wq_a     = (const float*)d_in[4];
    const float* Wkv_a    = (const float*)d_in[5];
    const float* qx_scale = (const float*)d_in[6];
    const float* qa_scale = (const float*)d_in[7];
    const float* kx_scale = (const float*)d_in[8];
    const float* ka_scale = (const float*)d_in[9];
    float* out = (float*)d_out;

    rope_invf_kernel<<<1, 64>>>();
    rope_table_kernel<<<(NN * DH + 255) / 256, 256>>>();

    // one launch: all fp16 casts (8 elems/thread)
    int cast_v8 = 2 * XV8 + 2 * WQV8 + 2 * WKV8;
    expand_all_kernel<<<(cast_v8 + 255) / 256, 256>>>(x, a, Wq_x, Wq_a, Wkv_x, Wkv_a);

    // one launch: all projections, hi-only K=1024 (512 Q + 64 KV, 2 CTAs/SM)
    int proj_smem = 2 * NSTAGE * STG_H * (int)sizeof(__half);  // 81920 B
    cudaFuncSetAttribute(proj_kernel, cudaFuncAttributeMaxDynamicSharedMemorySize, proj_smem);
    proj_kernel<<<576, 256, proj_smem>>>();

    prep_kernel<<<NT, 18 * 32>>>(qx_scale, qa_scale, kx_scale, ka_scale);

    int smem_bytes = (QH + 4 * TILE_H) * (int)sizeof(__half);  // 104448 B
    cudaFuncSetAttribute(attn_mma_kernel, cudaFuncAttributeMaxDynamicSharedMemorySize, smem_bytes);
    attn_mma_kernel<<<dim3(NN / 128, HEADS, BB), 256, smem_bytes>>>(out);
}